// round 13
// baseline (speedup 1.0000x reference)
#include <cuda_runtime.h>
#include <cstdint>

// nu_grid_sampler: out[b,c,n] = x[b,c,px,py], x:(8,128,256,256) f32,
// coords:(8,32768,2) f32, out:(8,128,32768) f32.
//
// R13: bucketed gather. R9/R12's limiter was predicated-slot LSU work: 64
// slots/warp/stage at ~8/32 active lanes (25% efficiency). Fix: counting-sort
// points by stage once per batch (4 tiny kernels), then each plane-block
// processes only bucket s during stage s -> dense coalesced entry LDG, dense
// LDS gather, dense STS scatter into a 128KB smem out-plane, and ONE TMA bulk
// store of the whole plane at the end. Reads stay TMA bulk (8 x 32KB stages,
// 3-buffer ring). All global stores leave the LSU; every out line written once.

#define GS_B 8
#define GS_C 128
#define GS_NX 256
#define GS_NY 256
#define GS_N 32768
#define GS_PIX (GS_NX * GS_NY)            // 65536
#define STAGE_PIX 8192                     // 32KB per stage
#define STAGE_BYTES (STAGE_PIX * 4)
#define NUM_STAGES 8
#define NUM_BUFS 3
#define K2_THREADS 1024
#define OBUF_BYTES (GS_N * 4)              // 128KB smem out-plane
#define SMEM_TOTAL (OBUF_BYTES + NUM_BUFS * STAGE_BYTES + 64)  // 229440

// scratch (static __device__, allowed)
__device__ unsigned g_idx[GS_B * GS_N];     // raw pixel index per point (1MB)
__device__ unsigned g_sorted[GS_B * GS_N];  // idx | (j<<16), bucketed (1MB)
__device__ int g_hist[GS_B * NUM_STAGES];
__device__ int g_boff[GS_B * (NUM_STAGES + 1)];
__device__ int g_cursor[GS_B * NUM_STAGES];

__device__ __forceinline__ unsigned compute_idx(float cy, float cx) {
    float pxf = fminf(fmaxf(cx * (float)(GS_NX - 1), 0.0f), (float)GS_NX);
    float pyf = fminf(fmaxf(cy * (float)(GS_NY - 1), 0.0f), (float)GS_NY);
    int idx = (int)pxf * GS_NY + (int)pyf;
    return (unsigned)min(idx, GS_PIX - 1);           // take_along_axis clamp
}

__global__ void zero_kernel() {
    int t = threadIdx.x;
    if (t < GS_B * NUM_STAGES) { g_hist[t] = 0; g_cursor[t] = 0; }
}

__global__ __launch_bounds__(256)
void hist_kernel(const float* __restrict__ coords) {
    __shared__ int lh[NUM_STAGES];
    int j = blockIdx.x * 256 + threadIdx.x;
    int b = blockIdx.y;
    if (threadIdx.x < NUM_STAGES) lh[threadIdx.x] = 0;
    __syncthreads();
    float2 co = reinterpret_cast<const float2*>(coords)[(size_t)b * GS_N + j];
    unsigned idx = compute_idx(co.x, co.y);
    g_idx[b * GS_N + j] = idx;
    atomicAdd(&lh[idx >> 13], 1);
    __syncthreads();
    if (threadIdx.x < NUM_STAGES)
        atomicAdd(&g_hist[b * NUM_STAGES + threadIdx.x], lh[threadIdx.x]);
}

__global__ void prefix_kernel() {
    int b = threadIdx.x;
    if (b < GS_B) {
        int run = 0;
        for (int s = 0; s < NUM_STAGES; ++s) {
            g_boff[b * (NUM_STAGES + 1) + s] = run;
            g_cursor[b * NUM_STAGES + s] = run;
            run += g_hist[b * NUM_STAGES + s];
        }
        g_boff[b * (NUM_STAGES + 1) + NUM_STAGES] = run;   // = 32768
    }
}

__global__ __launch_bounds__(256)
void scatter_kernel() {
    __shared__ int lh[NUM_STAGES], lbase[NUM_STAGES];
    int j = blockIdx.x * 256 + threadIdx.x;
    int b = blockIdx.y;
    unsigned idx = g_idx[b * GS_N + j];
    int s = idx >> 13;
    if (threadIdx.x < NUM_STAGES) lh[threadIdx.x] = 0;
    __syncthreads();
    int r = atomicAdd(&lh[s], 1);
    __syncthreads();
    if (threadIdx.x < NUM_STAGES)
        lbase[threadIdx.x] = atomicAdd(&g_cursor[b * NUM_STAGES + threadIdx.x],
                                       lh[threadIdx.x]);
    __syncthreads();
    g_sorted[b * GS_N + lbase[s] + r] = idx | ((unsigned)j << 16);
}

__device__ __forceinline__ uint32_t smem_u32(const void* p) {
    uint32_t a;
    asm("{ .reg .u64 t; cvta.to.shared.u64 t, %1; cvt.u32.u64 %0, t; }"
        : "=r"(a) : "l"(p));
    return a;
}

__device__ __forceinline__ void bulk_load_stage(uint32_t smem_dst, const float* gsrc,
                                                uint32_t mbar) {
    asm volatile("mbarrier.arrive.expect_tx.shared.b64 _, [%0], %1;"
                 :: "r"(mbar), "r"((unsigned)STAGE_BYTES) : "memory");
    asm volatile("cp.async.bulk.shared::cta.global.mbarrier::complete_tx::bytes "
                 "[%0], [%1], %2, [%3];"
                 :: "r"(smem_dst), "l"(gsrc), "r"((unsigned)STAGE_BYTES), "r"(mbar)
                 : "memory");
}

__device__ __forceinline__ void mbar_wait(uint32_t mbar, unsigned phase) {
    asm volatile(
        "{\n\t"
        ".reg .pred P;\n\t"
        "LAB_WAIT_%=:\n\t"
        "mbarrier.try_wait.parity.acquire.cta.shared::cta.b64 P, [%0], %1, 0x989680;\n\t"
        "@P bra.uni LAB_DONE_%=;\n\t"
        "bra.uni LAB_WAIT_%=;\n\t"
        "LAB_DONE_%=:\n\t"
        "}"
        :: "r"(mbar), "r"(phase) : "memory");
}

__global__ __launch_bounds__(K2_THREADS, 1)
void gather_kernel(const float* __restrict__ x, float* __restrict__ out) {
    extern __shared__ float smem[];
    // layout: obuf[32768] | stage[3][8192] | mbar[3]
    float* obuf = smem;
    float* stage0 = smem + GS_N;
    const int tid = threadIdx.x;
    const int bc  = blockIdx.x;                      // b*128 + c
    const int b   = bc >> 7;

    const float* __restrict__ plane = x + ((size_t)bc << 16);
    const unsigned* __restrict__ ents = g_sorted + b * GS_N;
    const int* __restrict__ boff = g_boff + b * (NUM_STAGES + 1);

    const uint32_t sb  = smem_u32(stage0);
    const uint32_t mb  = smem_u32(smem) + OBUF_BYTES + NUM_BUFS * STAGE_BYTES;

    if (tid == 0) {
        #pragma unroll
        for (int q = 0; q < NUM_BUFS; ++q)
            asm volatile("mbarrier.init.shared.b64 [%0], 1;"
                         :: "r"(mb + q * 8) : "memory");
    }
    __syncthreads();

    if (tid == 0) {   // prefetch stages 0,1 (lookahead 2)
        bulk_load_stage(sb + 0 * STAGE_BYTES, plane + 0 * (size_t)STAGE_PIX, mb + 0);
        bulk_load_stage(sb + 1 * STAGE_BYTES, plane + 1 * (size_t)STAGE_PIX, mb + 8);
    }

    #pragma unroll
    for (int s = 0; s < NUM_STAGES; ++s) {
        // issue s+2 into buf (s+2)%3 (drained at end of stage s-1)
        if (tid == 0 && s + 2 < NUM_STAGES)
            bulk_load_stage(sb + ((s + 2) % NUM_BUFS) * STAGE_BYTES,
                            plane + (size_t)(s + 2) * STAGE_PIX,
                            mb + ((s + 2) % NUM_BUFS) * 8);

        mbar_wait(mb + (s % NUM_BUFS) * 8, (unsigned)(s / NUM_BUFS));

        const float* cur = stage0 + (s % NUM_BUFS) * STAGE_PIX;
        const int lo = boff[s], hiE = boff[s + 1];
        // dense: coalesced entry load, dense LDS gather, STS scatter into obuf
        for (int i = lo + tid; i < hiE; i += K2_THREADS) {
            unsigned e = __ldg(ents + i);
            obuf[e >> 16] = cur[e & (STAGE_PIX - 1)];
        }
        __syncthreads();   // stage s consumed before buf (s%3) rewritten at s+2
    }

    // one bulk TMA store of the finished 128KB out-plane
    asm volatile("fence.proxy.async.shared::cta;" ::: "memory");
    __syncthreads();
    if (tid == 0) {
        float* gdst = out + ((size_t)bc << 15);
        asm volatile("cp.async.bulk.global.shared::cta.bulk_group [%0], [%1], %2;"
                     :: "l"(gdst), "r"(smem_u32(obuf)), "r"((unsigned)OBUF_BYTES)
                     : "memory");
        asm volatile("cp.async.bulk.commit_group;" ::: "memory");
        asm volatile("cp.async.bulk.wait_group 0;" ::: "memory");
    }
}

extern "C" void kernel_launch(void* const* d_in, const int* in_sizes, int n_in,
                              void* d_out, int out_size) {
    const float* x      = (const float*)d_in[0];   // (8,128,256,256) f32
    const float* coords = (const float*)d_in[1];   // (8,32768,2) f32
    float* out          = (float*)d_out;           // (8,128,32768) f32

    static int smem_set = 0;
    if (!smem_set) {
        cudaFuncSetAttribute(gather_kernel,
                             cudaFuncAttributeMaxDynamicSharedMemorySize,
                             SMEM_TOTAL);
        smem_set = 1;
    }

    zero_kernel<<<1, 64>>>();
    hist_kernel<<<dim3(GS_N / 256, GS_B), 256>>>(coords);
    prefix_kernel<<<1, 32>>>();
    scatter_kernel<<<dim3(GS_N / 256, GS_B), 256>>>();
    gather_kernel<<<GS_B * GS_C, K2_THREADS, SMEM_TOTAL>>>(x, out);
}

// round 14
// speedup vs baseline: 1.2744x; 1.2744x over previous
#include <cuda_runtime.h>
#include <cstdint>

// nu_grid_sampler: out[b,c,n] = x[b,c,px,py], x:(8,128,256,256) f32,
// coords:(8,32768,2) f32, out:(8,128,32768) f32.
//
// R14: counting-sort points per batch by 128B LINE (idx>>5, 2048 buckets).
// Sorted entries make direct global gathers near-coalesced (warp's 32 entries
// span ~2-3 lines; each plane line holds ~16 sorted-adjacent points -> one
// fetch, immediate consumption). No smem staging / TMA read pipeline / stage
// predication at all. smem holds the 128KB out-plane (STS scatter), flushed
// by ONE cp.async.bulk store. Sort: 4 tiny kernels, amortized over 128 planes.

#define GS_B 8
#define GS_C 128
#define GS_NX 256
#define GS_NY 256
#define GS_N 32768
#define GS_PIX (GS_NX * GS_NY)     // 65536
#define NBUCK 2048                  // idx>>5 : one 128B line per bucket
#define K2_THREADS 1024
#define ITERS (GS_N / K2_THREADS)   // 32
#define OBUF_BYTES (GS_N * 4)       // 128KB

__device__ unsigned g_idx[GS_B * GS_N];      // raw pixel idx per point
__device__ unsigned g_sorted[GS_B * GS_N];   // idx | (j<<16), line-sorted
__device__ int g_hist[GS_B * NBUCK];
__device__ int g_cursor[GS_B * NBUCK];

__device__ __forceinline__ unsigned compute_idx(float cy, float cx) {
    float pxf = fminf(fmaxf(cx * (float)(GS_NX - 1), 0.0f), (float)GS_NX);
    float pyf = fminf(fmaxf(cy * (float)(GS_NY - 1), 0.0f), (float)GS_NY);
    int idx = (int)pxf * GS_NY + (int)pyf;
    return (unsigned)min(idx, GS_PIX - 1);   // take_along_axis clamp
}

__global__ __launch_bounds__(1024)
void zero_kernel() {
    int t = blockIdx.x * 1024 + threadIdx.x;
    if (t < GS_B * NBUCK) g_hist[t] = 0;
}

__global__ __launch_bounds__(1024)
void hist_kernel(const float* __restrict__ coords) {
    __shared__ int lh[NBUCK];
    const int t = threadIdx.x;
    const int b = blockIdx.y;
    const int j = blockIdx.x * 1024 + t;
    lh[t] = 0; lh[t + 1024] = 0;
    __syncthreads();
    float2 co = reinterpret_cast<const float2*>(coords)[(size_t)b * GS_N + j];
    unsigned idx = compute_idx(co.x, co.y);
    g_idx[b * GS_N + j] = idx;
    atomicAdd(&lh[idx >> 5], 1);
    __syncthreads();
    if (lh[t])        atomicAdd(&g_hist[b * NBUCK + t],        lh[t]);
    if (lh[t + 1024]) atomicAdd(&g_hist[b * NBUCK + t + 1024], lh[t + 1024]);
}

__global__ __launch_bounds__(1024)
void prefix_kernel() {            // one block per batch: exclusive scan of 2048
    __shared__ int sc[NBUCK];
    __shared__ int ps[1024];
    const int t = threadIdx.x;
    const int b = blockIdx.x;
    sc[t]        = g_hist[b * NBUCK + t];
    sc[t + 1024] = g_hist[b * NBUCK + t + 1024];
    __syncthreads();
    int pairsum = sc[2 * t] + sc[2 * t + 1];
    ps[t] = pairsum;
    __syncthreads();
    for (int off = 1; off < 1024; off <<= 1) {      // Hillis-Steele inclusive
        int v = (t >= off) ? ps[t - off] : 0;
        __syncthreads();
        ps[t] += v;
        __syncthreads();
    }
    int base = ps[t] - pairsum;                      // exclusive over pairs
    g_cursor[b * NBUCK + 2 * t]     = base;
    g_cursor[b * NBUCK + 2 * t + 1] = base + sc[2 * t];
}

__global__ __launch_bounds__(1024)
void scatter_kernel() {
    __shared__ int lh[NBUCK];
    __shared__ int lbase[NBUCK];
    const int t = threadIdx.x;
    const int b = blockIdx.y;
    const int j = blockIdx.x * 1024 + t;
    lh[t] = 0; lh[t + 1024] = 0;
    __syncthreads();
    unsigned idx = g_idx[b * GS_N + j];
    int s = idx >> 5;
    int r = atomicAdd(&lh[s], 1);
    __syncthreads();
    if (lh[t])        lbase[t]        = atomicAdd(&g_cursor[b * NBUCK + t],        lh[t]);
    if (lh[t + 1024]) lbase[t + 1024] = atomicAdd(&g_cursor[b * NBUCK + t + 1024], lh[t + 1024]);
    __syncthreads();
    g_sorted[b * GS_N + lbase[s] + r] = idx | ((unsigned)j << 16);
}

__device__ __forceinline__ uint32_t smem_u32(const void* p) {
    uint32_t a;
    asm("{ .reg .u64 t; cvta.to.shared.u64 t, %1; cvt.u32.u64 %0, t; }"
        : "=r"(a) : "l"(p));
    return a;
}

__global__ __launch_bounds__(K2_THREADS, 1)
void gather_kernel(const float* __restrict__ x, float* __restrict__ out) {
    extern __shared__ float obuf[];              // 32768 floats = 128KB
    const int tid = threadIdx.x;
    const int bc  = blockIdx.x;                  // b*128 + c
    const int b   = bc >> 7;

    const float* __restrict__ plane    = x + ((size_t)bc << 16);
    const unsigned* __restrict__ ents  = g_sorted + b * GS_N;

    // 32 iterations: coalesced entry load, near-coalesced sorted gather,
    // STS scatter into the smem out-plane.
    #pragma unroll 8
    for (int it = 0; it < ITERS; ++it) {
        unsigned e = __ldg(ents + (it << 10) + tid);
        obuf[e >> 16] = __ldg(plane + (e & 0xFFFFu));
    }

    asm volatile("fence.proxy.async.shared::cta;" ::: "memory");
    __syncthreads();
    if (tid == 0) {
        float* gdst = out + ((size_t)bc << 15);
        asm volatile("cp.async.bulk.global.shared::cta.bulk_group [%0], [%1], %2;"
                     :: "l"(gdst), "r"(smem_u32(obuf)), "r"((unsigned)OBUF_BYTES)
                     : "memory");
        asm volatile("cp.async.bulk.commit_group;" ::: "memory");
        asm volatile("cp.async.bulk.wait_group 0;" ::: "memory");
    }
}

extern "C" void kernel_launch(void* const* d_in, const int* in_sizes, int n_in,
                              void* d_out, int out_size) {
    const float* x      = (const float*)d_in[0];   // (8,128,256,256) f32
    const float* coords = (const float*)d_in[1];   // (8,32768,2) f32
    float* out          = (float*)d_out;           // (8,128,32768) f32

    static int smem_set = 0;
    if (!smem_set) {
        cudaFuncSetAttribute(gather_kernel,
                             cudaFuncAttributeMaxDynamicSharedMemorySize,
                             OBUF_BYTES);
        smem_set = 1;
    }

    zero_kernel<<<(GS_B * NBUCK + 1023) / 1024, 1024>>>();
    hist_kernel<<<dim3(GS_N / 1024, GS_B), 1024>>>(coords);
    prefix_kernel<<<GS_B, 1024>>>();
    scatter_kernel<<<dim3(GS_N / 1024, GS_B), 1024>>>();
    gather_kernel<<<GS_B * GS_C, K2_THREADS, OBUF_BYTES>>>(x, out);
}